// round 2
// baseline (speedup 1.0000x reference)
#include <cuda_runtime.h>

// ---------------------------------------------------------------- constants
#define T_LEN  512
#define BATCH  64
#define HSZ    1024
#define GSZ    4096          // 4*H
#define NLAYER 2
#define M_GEMM (T_LEN*BATCH) // 32768

#define NBLK_LSTM 128
#define NTHR_LSTM 128
// smem floats: Ws[1024][32] + hs[128][64] + gs[64][32] + cs[64][8]
#define WS_FLOATS (1024*32)
#define HS_FLOATS (128*64)
#define GS_FLOATS (64*32)
#define CS_FLOATS (64*8)
#define SMEM_LSTM_BYTES ((WS_FLOATS + HS_FLOATS + GS_FLOATS + CS_FLOATS) * 4)

// ---------------------------------------------------------------- scratch
__device__ float g_gx[(size_t)T_LEN * BATCH * GSZ];   // 536 MB gate preacts
__device__ float g_seq[(size_t)T_LEN * BATCH * HSZ];  // layer-1 outputs
__device__ float g_hbuf[2][HSZ * BATCH];              // h state, transposed [H][B]
__device__ unsigned g_cnt;
__device__ volatile unsigned g_gen;

// ---------------------------------------------------------------- grid barrier
__device__ __forceinline__ void grid_barrier(int nblk) {
    __syncthreads();
    if (threadIdx.x == 0) {
        __threadfence();
        unsigned mygen = g_gen;
        unsigned prev = atomicAdd(&g_cnt, 1u);
        if (prev == (unsigned)(nblk - 1)) {
            g_cnt = 0;
            __threadfence();
            g_gen = mygen + 1u;
        } else {
            while (g_gen == mygen) { __nanosleep(64); }
        }
        __threadfence();
    }
    __syncthreads();
}

// ---------------------------------------------------------------- SGEMM (NT) + bias
// C[m][n] = sum_k A[m][k] * W[n][k] + bias[n]
// A: [32768,1024] row-major, W: [4096,1024] row-major, C = g_gx [32768,4096]
// Block tile 128x128, BK=8, 256 threads, 8x8 per thread.
__global__ __launch_bounds__(256) void sgemm_nt_bias(
    const float* __restrict__ Aext, int a_from_seq,
    const float* __restrict__ W,
    const float* __restrict__ bias)
{
    const int K = HSZ;
    const int N = GSZ;
    const float* A = a_from_seq ? g_seq : Aext;

    __shared__ float As[8][128];
    __shared__ float Bs[8][128];

    const int tid = threadIdx.x;
    const int mt = blockIdx.y * 128;
    const int nt = blockIdx.x * 128;

    const int lrow = tid >> 1;          // 0..127
    const int lk   = (tid & 1) * 4;     // 0 or 4
    const float* Aptr = A + (size_t)(mt + lrow) * K + lk;
    const float* Wptr = W + (size_t)(nt + lrow) * K + lk;

    const int tx = tid & 15;            // col group
    const int ty = tid >> 4;            // row group

    float acc[8][8];
#pragma unroll
    for (int i = 0; i < 8; i++)
#pragma unroll
        for (int j = 0; j < 8; j++) acc[i][j] = 0.f;

    for (int k0 = 0; k0 < K; k0 += 8) {
        float4 av = *(const float4*)(Aptr + k0);
        float4 wv = *(const float4*)(Wptr + k0);
        As[lk + 0][lrow] = av.x; As[lk + 1][lrow] = av.y;
        As[lk + 2][lrow] = av.z; As[lk + 3][lrow] = av.w;
        Bs[lk + 0][lrow] = wv.x; Bs[lk + 1][lrow] = wv.y;
        Bs[lk + 2][lrow] = wv.z; Bs[lk + 3][lrow] = wv.w;
        __syncthreads();
#pragma unroll
        for (int k = 0; k < 8; k++) {
            float a[8], bb[8];
            *(float4*)&a[0]  = *(const float4*)&As[k][ty * 4];
            *(float4*)&a[4]  = *(const float4*)&As[k][64 + ty * 4];
            *(float4*)&bb[0] = *(const float4*)&Bs[k][tx * 4];
            *(float4*)&bb[4] = *(const float4*)&Bs[k][64 + tx * 4];
#pragma unroll
            for (int i = 0; i < 8; i++)
#pragma unroll
                for (int j = 0; j < 8; j++) acc[i][j] += a[i] * bb[j];
        }
        __syncthreads();
    }

#pragma unroll
    for (int i = 0; i < 8; i++) {
        int m = mt + ((i < 4) ? (ty * 4 + i) : (64 + ty * 4 + (i - 4)));
#pragma unroll
        for (int j = 0; j < 8; j++) {
            int n = nt + ((j < 4) ? (tx * 4 + j) : (64 + tx * 4 + (j - 4)));
            g_gx[(size_t)m * N + n] = acc[i][j] + bias[n];
        }
    }
}

// ---------------------------------------------------------------- persistent LSTM layer
// 128 blocks, block b owns hidden units j0 = 8*b .. +8  (32 gate rows).
// Whh slice cached in smem k-major for all 512 steps. h double-buffered in
// global, transposed [H][B]. One grid barrier per timestep.
__global__ __launch_bounds__(NTHR_LSTM, 1) void lstm_layer_kernel(
    const float* __restrict__ Whh,   // [4H, H] for this layer
    const float* __restrict__ h0,    // [B, H]
    const float* __restrict__ c0,    // [B, H]
    float* __restrict__ seq_ext, int seq_internal,
    float* __restrict__ hn,          // [B, H]
    float* __restrict__ cn)          // [B, H]
{
    extern __shared__ float sm[];
    float* Ws = sm;                    // [1024][32] k-major
    float* hs = Ws + WS_FLOATS;        // [128][64]  k-major chunk of h
    float* gs = hs + HS_FLOATS;        // [64][32]   staged gate preacts
    float* cs = gs + GS_FLOATS;        // [64][8]    persistent cell state

    float* seq_out = seq_internal ? g_seq : seq_ext;

    const int tid = threadIdx.x;
    const int blk = blockIdx.x;        // 0..127
    const int j0  = blk * 8;

    // ---- load Whh slice (32 rows x 1024) transposed to k-major smem ----
    for (int idx = tid; idx < 32 * 256; idx += NTHR_LSTM) {
        int c  = idx >> 8;             // 0..31  (local gate col: q*8+jj)
        int kq = idx & 255;            // k/4
        int q = c >> 3, jj = c & 7;
        const float4 v = *(const float4*)(Whh + (size_t)(q * HSZ + j0 + jj) * HSZ + kq * 4);
        Ws[(kq * 4 + 0) * 32 + c] = v.x;
        Ws[(kq * 4 + 1) * 32 + c] = v.y;
        Ws[(kq * 4 + 2) * 32 + c] = v.z;
        Ws[(kq * 4 + 3) * 32 + c] = v.w;
    }
    // ---- init h buffer (transposed) and cell state ----
    for (int idx = tid; idx < 8 * 64; idx += NTHR_LSTM) {
        int jj = idx >> 6, r = idx & 63;
        g_hbuf[0][(j0 + jj) * BATCH + r] = h0[r * HSZ + j0 + jj];
    }
    for (int idx = tid; idx < 64 * 8; idx += NTHR_LSTM) {
        int r = idx >> 3, jj = idx & 7;
        cs[r * 8 + jj] = c0[r * HSZ + j0 + jj];
    }
    grid_barrier(NBLK_LSTM);

    // GEMM thread mapping: 4 warps; warp tile 32r x 16c; thread tile 4r x 4c
    const int w = tid >> 5, lane = tid & 31;
    const int wr = w & 1, wc = w >> 1;
    const int lr = lane & 7, lc = lane >> 3;
    const int r0 = wr * 32 + lr * 4;
    const int cc0 = wc * 16 + lc * 4;

    for (int t = 0; t < T_LEN; t++) {
        const float* hbuf = g_hbuf[t & 1];
        float* hnext = g_hbuf[(t + 1) & 1];

        float acc[4][4];
#pragma unroll
        for (int i = 0; i < 4; i++)
#pragma unroll
            for (int j = 0; j < 4; j++) acc[i][j] = 0.f;

        for (int kc = 0; kc < HSZ; kc += 128) {
            __syncthreads();   // previous chunk consumers done
            // coalesced copy: hbuf is [H][B], chunk = 128*64 contiguous floats
            const float4* src = (const float4*)(hbuf + kc * BATCH);
            float4* dst = (float4*)hs;
            for (int idx = tid; idx < (128 * 64) / 4; idx += NTHR_LSTM)
                dst[idx] = src[idx];
            __syncthreads();

            const float* wp = Ws + kc * 32 + cc0;
#pragma unroll 8
            for (int k = 0; k < 128; k++) {
                const float4 hv = *(const float4*)(hs + k * 64 + r0);
                const float4 wv = *(const float4*)(wp + k * 32);
                acc[0][0] += hv.x * wv.x; acc[0][1] += hv.x * wv.y;
                acc[0][2] += hv.x * wv.z; acc[0][3] += hv.x * wv.w;
                acc[1][0] += hv.y * wv.x; acc[1][1] += hv.y * wv.y;
                acc[1][2] += hv.y * wv.z; acc[1][3] += hv.y * wv.w;
                acc[2][0] += hv.z * wv.x; acc[2][1] += hv.z * wv.y;
                acc[2][2] += hv.z * wv.z; acc[2][3] += hv.z * wv.w;
                acc[3][0] += hv.w * wv.x; acc[3][1] += hv.w * wv.y;
                acc[3][2] += hv.w * wv.z; acc[3][3] += hv.w * wv.w;
            }
        }

        // stage gate preacts to smem so gating threads can gather all 4 gates
#pragma unroll
        for (int i = 0; i < 4; i++)
#pragma unroll
            for (int j = 0; j < 4; j++)
                gs[(r0 + i) * 32 + (cc0 + j)] = acc[i][j];
        __syncthreads();

        // gating: 512 (r,jj) pairs / 128 threads = 4 each
        const float* gxt = g_gx + (size_t)t * BATCH * GSZ;
#pragma unroll
        for (int ii = 0; ii < 4; ii++) {
            int p = tid + ii * NTHR_LSTM;
            int r = p >> 3, jj = p & 7;
            int j = j0 + jj;
            float gi = gs[r * 32 + jj]      + gxt[(size_t)r * GSZ + 0 * HSZ + j];
            float gf = gs[r * 32 + 8 + jj]  + gxt[(size_t)r * GSZ + 1 * HSZ + j];
            float gg = gs[r * 32 + 16 + jj] + gxt[(size_t)r * GSZ + 2 * HSZ + j];
            float go = gs[r * 32 + 24 + jj] + gxt[(size_t)r * GSZ + 3 * HSZ + j];
            float iv = 1.f / (1.f + __expf(-gi));
            float fv = 1.f / (1.f + __expf(-gf));
            float gv = tanhf(gg);
            float ov = 1.f / (1.f + __expf(-go));
            float cv = fv * cs[r * 8 + jj] + iv * gv;
            float hv = ov * tanhf(cv);
            cs[r * 8 + jj] = cv;
            hnext[j * BATCH + r] = hv;
            seq_out[((size_t)t * BATCH + r) * HSZ + j] = hv;
            if (t == T_LEN - 1) {
                hn[r * HSZ + j] = hv;
                cn[r * HSZ + j] = cv;
            }
        }
        grid_barrier(NBLK_LSTM);
    }
}

// ---------------------------------------------------------------- launch
extern "C" void kernel_launch(void* const* d_in, const int* in_sizes, int n_in,
                              void* d_out, int out_size) {
    const float* x   = (const float*)d_in[0];
    const float* Wih = (const float*)d_in[1];
    const float* Whh = (const float*)d_in[2];
    const float* b   = (const float*)d_in[3];
    const float* h0  = (const float*)d_in[4];
    const float* c0  = (const float*)d_in[5];

    float* out     = (float*)d_out;
    float* out_seq = out;                                    // [T,B,H]
    float* out_hn  = out + (size_t)T_LEN * BATCH * HSZ;      // [L,B,H]
    float* out_cn  = out_hn + (size_t)NLAYER * BATCH * HSZ;  // [L,B,H]

    cudaFuncSetAttribute(lstm_layer_kernel,
                         cudaFuncAttributeMaxDynamicSharedMemorySize,
                         SMEM_LSTM_BYTES);

    dim3 ggrid(GSZ / 128, M_GEMM / 128);   // (32, 256)

    // ---- layer 0 ----
    sgemm_nt_bias<<<ggrid, 256>>>(x, 0, Wih, b);
    lstm_layer_kernel<<<NBLK_LSTM, NTHR_LSTM, SMEM_LSTM_BYTES>>>(
        Whh, h0, c0,
        /*seq_ext=*/nullptr, /*seq_internal=*/1,
        out_hn, out_cn);

    // ---- layer 1 ----
    sgemm_nt_bias<<<ggrid, 256>>>(nullptr, 1,
                                  Wih + (size_t)GSZ * HSZ,
                                  b + GSZ);
    lstm_layer_kernel<<<NBLK_LSTM, NTHR_LSTM, SMEM_LSTM_BYTES>>>(
        Whh + (size_t)GSZ * HSZ,
        h0 + (size_t)BATCH * HSZ,
        c0 + (size_t)BATCH * HSZ,
        out_seq, /*seq_internal=*/0,
        out_hn + (size_t)BATCH * HSZ,
        out_cn + (size_t)BATCH * HSZ);
}

// round 3
// speedup vs baseline: 1.0022x; 1.0022x over previous
#include <cuda_runtime.h>

// ---------------------------------------------------------------- constants
#define T_LEN  512
#define BATCH  64
#define HSZ    1024
#define GSZ    4096          // 4*H
#define NLAYER 2
#define M_GEMM (T_LEN*BATCH) // 32768

#define NBLK_LSTM 128
#define NTHR_LSTM 128
// smem floats: Ws[1024][32] + hs[128][64] + gs[64][32] + cs[64][8]
#define WS_FLOATS (1024*32)
#define HS_FLOATS (128*64)
#define GS_FLOATS (64*32)
#define CS_FLOATS (64*8)
#define SMEM_LSTM_BYTES ((WS_FLOATS + HS_FLOATS + GS_FLOATS + CS_FLOATS) * 4)

// ---------------------------------------------------------------- scratch
__device__ float g_gx[(size_t)T_LEN * BATCH * GSZ];   // 536 MB gate preacts
__device__ float g_seq[(size_t)T_LEN * BATCH * HSZ];  // layer-1 outputs
__device__ float g_hbuf[2][HSZ * BATCH];              // h state, transposed [H][B]
__device__ unsigned g_cnt;
__device__ volatile unsigned g_gen;

// ---------------------------------------------------------------- grid barrier
__device__ __forceinline__ void grid_barrier(int nblk) {
    __syncthreads();
    if (threadIdx.x == 0) {
        __threadfence();
        unsigned mygen = g_gen;
        unsigned prev = atomicAdd(&g_cnt, 1u);
        if (prev == (unsigned)(nblk - 1)) {
            g_cnt = 0;
            __threadfence();
            g_gen = mygen + 1u;
        } else {
            while (g_gen == mygen) { __nanosleep(64); }
        }
        __threadfence();
    }
    __syncthreads();
}

// ---------------------------------------------------------------- SGEMM (NT) + bias
// C[m][n] = sum_k A[m][k] * W[n][k] + bias[n]
// A: [32768,1024] row-major, W: [4096,1024] row-major, C = g_gx [32768,4096]
// Block tile 128x128, BK=8, 256 threads, 8x8 per thread.
__global__ __launch_bounds__(256) void sgemm_nt_bias(
    const float* __restrict__ Aext, int a_from_seq,
    const float* __restrict__ W,
    const float* __restrict__ bias)
{
    const int K = HSZ;
    const int N = GSZ;
    const float* A = a_from_seq ? g_seq : Aext;

    __shared__ float As[8][128];
    __shared__ float Bs[8][128];

    const int tid = threadIdx.x;
    const int mt = blockIdx.y * 128;
    const int nt = blockIdx.x * 128;

    const int lrow = tid >> 1;          // 0..127
    const int lk   = (tid & 1) * 4;     // 0 or 4
    const float* Aptr = A + (size_t)(mt + lrow) * K + lk;
    const float* Wptr = W + (size_t)(nt + lrow) * K + lk;

    const int tx = tid & 15;            // col group
    const int ty = tid >> 4;            // row group

    float acc[8][8];
#pragma unroll
    for (int i = 0; i < 8; i++)
#pragma unroll
        for (int j = 0; j < 8; j++) acc[i][j] = 0.f;

    for (int k0 = 0; k0 < K; k0 += 8) {
        float4 av = *(const float4*)(Aptr + k0);
        float4 wv = *(const float4*)(Wptr + k0);
        As[lk + 0][lrow] = av.x; As[lk + 1][lrow] = av.y;
        As[lk + 2][lrow] = av.z; As[lk + 3][lrow] = av.w;
        Bs[lk + 0][lrow] = wv.x; Bs[lk + 1][lrow] = wv.y;
        Bs[lk + 2][lrow] = wv.z; Bs[lk + 3][lrow] = wv.w;
        __syncthreads();
#pragma unroll
        for (int k = 0; k < 8; k++) {
            float a[8], bb[8];
            *(float4*)&a[0]  = *(const float4*)&As[k][ty * 4];
            *(float4*)&a[4]  = *(const float4*)&As[k][64 + ty * 4];
            *(float4*)&bb[0] = *(const float4*)&Bs[k][tx * 4];
            *(float4*)&bb[4] = *(const float4*)&Bs[k][64 + tx * 4];
#pragma unroll
            for (int i = 0; i < 8; i++)
#pragma unroll
                for (int j = 0; j < 8; j++) acc[i][j] += a[i] * bb[j];
        }
        __syncthreads();
    }

#pragma unroll
    for (int i = 0; i < 8; i++) {
        int m = mt + ((i < 4) ? (ty * 4 + i) : (64 + ty * 4 + (i - 4)));
#pragma unroll
        for (int j = 0; j < 8; j++) {
            int n = nt + ((j < 4) ? (tx * 4 + j) : (64 + tx * 4 + (j - 4)));
            g_gx[(size_t)m * N + n] = acc[i][j] + bias[n];
        }
    }
}

// ---------------------------------------------------------------- persistent LSTM layer
// 128 blocks, block b owns hidden units j0 = 8*b .. +8  (32 gate rows).
// Whh slice cached in smem k-major for all 512 steps. h double-buffered in
// global, transposed [H][B]. One grid barrier per timestep.
__global__ __launch_bounds__(NTHR_LSTM, 1) void lstm_layer_kernel(
    const float* __restrict__ Whh,   // [4H, H] for this layer
    const float* __restrict__ h0,    // [B, H]
    const float* __restrict__ c0,    // [B, H]
    float* __restrict__ seq_ext, int seq_internal,
    float* __restrict__ hn,          // [B, H]
    float* __restrict__ cn)          // [B, H]
{
    extern __shared__ float sm[];
    float* Ws = sm;                    // [1024][32] k-major
    float* hs = Ws + WS_FLOATS;        // [128][64]  k-major chunk of h
    float* gs = hs + HS_FLOATS;        // [64][32]   staged gate preacts
    float* cs = gs + GS_FLOATS;        // [64][8]    persistent cell state

    float* seq_out = seq_internal ? g_seq : seq_ext;

    const int tid = threadIdx.x;
    const int blk = blockIdx.x;        // 0..127
    const int j0  = blk * 8;

    // ---- load Whh slice (32 rows x 1024) transposed to k-major smem ----
    for (int idx = tid; idx < 32 * 256; idx += NTHR_LSTM) {
        int c  = idx >> 8;             // 0..31  (local gate col: q*8+jj)
        int kq = idx & 255;            // k/4
        int q = c >> 3, jj = c & 7;
        const float4 v = *(const float4*)(Whh + (size_t)(q * HSZ + j0 + jj) * HSZ + kq * 4);
        Ws[(kq * 4 + 0) * 32 + c] = v.x;
        Ws[(kq * 4 + 1) * 32 + c] = v.y;
        Ws[(kq * 4 + 2) * 32 + c] = v.z;
        Ws[(kq * 4 + 3) * 32 + c] = v.w;
    }
    // ---- init h buffer (transposed) and cell state ----
    for (int idx = tid; idx < 8 * 64; idx += NTHR_LSTM) {
        int jj = idx >> 6, r = idx & 63;
        g_hbuf[0][(j0 + jj) * BATCH + r] = h0[r * HSZ + j0 + jj];
    }
    for (int idx = tid; idx < 64 * 8; idx += NTHR_LSTM) {
        int r = idx >> 3, jj = idx & 7;
        cs[r * 8 + jj] = c0[r * HSZ + j0 + jj];
    }
    grid_barrier(NBLK_LSTM);

    // GEMM thread mapping: 4 warps; warp tile 32r x 16c; thread tile 4r x 4c
    const int w = tid >> 5, lane = tid & 31;
    const int wr = w & 1, wc = w >> 1;
    const int lr = lane & 7, lc = lane >> 3;
    const int r0 = wr * 32 + lr * 4;
    const int cc0 = wc * 16 + lc * 4;

    for (int t = 0; t < T_LEN; t++) {
        const float* hbuf = g_hbuf[t & 1];
        float* hnext = g_hbuf[(t + 1) & 1];

        float acc[4][4];
#pragma unroll
        for (int i = 0; i < 4; i++)
#pragma unroll
            for (int j = 0; j < 4; j++) acc[i][j] = 0.f;

        for (int kc = 0; kc < HSZ; kc += 128) {
            __syncthreads();   // previous chunk consumers done
            // coalesced copy: hbuf is [H][B], chunk = 128*64 contiguous floats
            const float4* src = (const float4*)(hbuf + kc * BATCH);
            float4* dst = (float4*)hs;
            for (int idx = tid; idx < (128 * 64) / 4; idx += NTHR_LSTM)
                dst[idx] = src[idx];
            __syncthreads();

            const float* wp = Ws + kc * 32 + cc0;
#pragma unroll 8
            for (int k = 0; k < 128; k++) {
                const float4 hv = *(const float4*)(hs + k * 64 + r0);
                const float4 wv = *(const float4*)(wp + k * 32);
                acc[0][0] += hv.x * wv.x; acc[0][1] += hv.x * wv.y;
                acc[0][2] += hv.x * wv.z; acc[0][3] += hv.x * wv.w;
                acc[1][0] += hv.y * wv.x; acc[1][1] += hv.y * wv.y;
                acc[1][2] += hv.y * wv.z; acc[1][3] += hv.y * wv.w;
                acc[2][0] += hv.z * wv.x; acc[2][1] += hv.z * wv.y;
                acc[2][2] += hv.z * wv.z; acc[2][3] += hv.z * wv.w;
                acc[3][0] += hv.w * wv.x; acc[3][1] += hv.w * wv.y;
                acc[3][2] += hv.w * wv.z; acc[3][3] += hv.w * wv.w;
            }
        }

        // stage gate preacts to smem so gating threads can gather all 4 gates
#pragma unroll
        for (int i = 0; i < 4; i++)
#pragma unroll
            for (int j = 0; j < 4; j++)
                gs[(r0 + i) * 32 + (cc0 + j)] = acc[i][j];
        __syncthreads();

        // gating: 512 (r,jj) pairs / 128 threads = 4 each
        const float* gxt = g_gx + (size_t)t * BATCH * GSZ;
#pragma unroll
        for (int ii = 0; ii < 4; ii++) {
            int p = tid + ii * NTHR_LSTM;
            int r = p >> 3, jj = p & 7;
            int j = j0 + jj;
            float gi = gs[r * 32 + jj]      + gxt[(size_t)r * GSZ + 0 * HSZ + j];
            float gf = gs[r * 32 + 8 + jj]  + gxt[(size_t)r * GSZ + 1 * HSZ + j];
            float gg = gs[r * 32 + 16 + jj] + gxt[(size_t)r * GSZ + 2 * HSZ + j];
            float go = gs[r * 32 + 24 + jj] + gxt[(size_t)r * GSZ + 3 * HSZ + j];
            float iv = 1.f / (1.f + __expf(-gi));
            float fv = 1.f / (1.f + __expf(-gf));
            float gv = tanhf(gg);
            float ov = 1.f / (1.f + __expf(-go));
            float cv = fv * cs[r * 8 + jj] + iv * gv;
            float hv = ov * tanhf(cv);
            cs[r * 8 + jj] = cv;
            hnext[j * BATCH + r] = hv;
            seq_out[((size_t)t * BATCH + r) * HSZ + j] = hv;
            if (t == T_LEN - 1) {
                hn[r * HSZ + j] = hv;
                cn[r * HSZ + j] = cv;
            }
        }
        grid_barrier(NBLK_LSTM);
    }
}

// ---------------------------------------------------------------- launch
extern "C" void kernel_launch(void* const* d_in, const int* in_sizes, int n_in,
                              void* d_out, int out_size) {
    const float* x   = (const float*)d_in[0];
    const float* Wih = (const float*)d_in[1];
    const float* Whh = (const float*)d_in[2];
    const float* b   = (const float*)d_in[3];
    const float* h0  = (const float*)d_in[4];
    const float* c0  = (const float*)d_in[5];

    float* out     = (float*)d_out;
    float* out_seq = out;                                    // [T,B,H]
    float* out_hn  = out + (size_t)T_LEN * BATCH * HSZ;      // [L,B,H]
    float* out_cn  = out_hn + (size_t)NLAYER * BATCH * HSZ;  // [L,B,H]

    cudaFuncSetAttribute(lstm_layer_kernel,
                         cudaFuncAttributeMaxDynamicSharedMemorySize,
                         SMEM_LSTM_BYTES);

    dim3 ggrid(GSZ / 128, M_GEMM / 128);   // (32, 256)

    // ---- layer 0 ----
    sgemm_nt_bias<<<ggrid, 256>>>(x, 0, Wih, b);
    lstm_layer_kernel<<<NBLK_LSTM, NTHR_LSTM, SMEM_LSTM_BYTES>>>(
        Whh, h0, c0,
        /*seq_ext=*/nullptr, /*seq_internal=*/1,
        out_hn, out_cn);

    // ---- layer 1 ----
    sgemm_nt_bias<<<ggrid, 256>>>(nullptr, 1,
                                  Wih + (size_t)GSZ * HSZ,
                                  b + GSZ);
    lstm_layer_kernel<<<NBLK_LSTM, NTHR_LSTM, SMEM_LSTM_BYTES>>>(
        Whh + (size_t)GSZ * HSZ,
        h0 + (size_t)BATCH * HSZ,
        c0 + (size_t)BATCH * HSZ,
        out_seq, /*seq_internal=*/0,
        out_hn + (size_t)BATCH * HSZ,
        out_cn + (size_t)BATCH * HSZ);
}

// round 4
// speedup vs baseline: 3.1718x; 3.1649x over previous
#include <cuda_runtime.h>
#include <cuda_fp16.h>
#include <cstdint>

#define T_LEN  512
#define BATCH  64
#define HSZ    1024
#define GSZ    4096
#define MROWS  (T_LEN*BATCH)
#define NBLK   128
#define RT     256
#define GT     256

// ---------------- scratch ----------------
__device__ __half g_xh  [(size_t)MROWS*HSZ];
__device__ __half g_seqh[(size_t)MROWS*HSZ];
__device__ __half g_wih_h[(size_t)2*GSZ*HSZ];
__device__ __half g_whh_h[(size_t)2*GSZ*HSZ];
__device__ float  g_gx  [(size_t)MROWS*GSZ];
__device__ __half g_hbuf[2][BATCH*HSZ];
__device__ unsigned g_cnt;
__device__ volatile unsigned g_gen;

// ---------------- ptx helpers ----------------
__device__ __forceinline__ uint32_t smem_u32(const void* p) {
    uint32_t a;
    asm("{ .reg .u64 t; cvta.to.shared.u64 t, %1; cvt.u32.u64 %0, t; }" : "=r"(a) : "l"(p));
    return a;
}
__device__ __forceinline__ void cp16(uint32_t d, const void* s) {
    asm volatile("cp.async.cg.shared.global [%0], [%1], 16;" :: "r"(d), "l"(s));
}
__device__ __forceinline__ void cp_commit() { asm volatile("cp.async.commit_group;"); }
template<int N> __device__ __forceinline__ void cp_wait() {
    asm volatile("cp.async.wait_group %0;" :: "n"(N));
}
__device__ __forceinline__ void ldsm4(uint32_t& r0, uint32_t& r1, uint32_t& r2, uint32_t& r3, uint32_t a) {
    asm volatile("ldmatrix.sync.aligned.m8n8.x4.shared.b16 {%0,%1,%2,%3}, [%4];"
        : "=r"(r0), "=r"(r1), "=r"(r2), "=r"(r3) : "r"(a));
}
__device__ __forceinline__ void ldsm2(uint32_t& r0, uint32_t& r1, uint32_t a) {
    asm volatile("ldmatrix.sync.aligned.m8n8.x2.shared.b16 {%0,%1}, [%2];"
        : "=r"(r0), "=r"(r1) : "r"(a));
}
__device__ __forceinline__ void mma16816(float& c0, float& c1, float& c2, float& c3,
    uint32_t a0, uint32_t a1, uint32_t a2, uint32_t a3, uint32_t b0, uint32_t b1) {
    asm volatile("mma.sync.aligned.m16n8k16.row.col.f32.f16.f16.f32 "
        "{%0,%1,%2,%3}, {%4,%5,%6,%7}, {%8,%9}, {%0,%1,%2,%3};"
        : "+f"(c0), "+f"(c1), "+f"(c2), "+f"(c3)
        : "r"(a0), "r"(a1), "r"(a2), "r"(a3), "r"(b0), "r"(b1));
}
__device__ __forceinline__ void grid_barrier() {
    __threadfence();
    __syncthreads();
    if (threadIdx.x == 0) {
        unsigned mygen = g_gen;
        unsigned prev = atomicAdd(&g_cnt, 1u);
        if (prev == (unsigned)(NBLK - 1)) {
            g_cnt = 0; __threadfence(); g_gen = mygen + 1u;
        } else {
            while (g_gen == mygen) { __nanosleep(32); }
        }
        __threadfence();
    }
    __syncthreads();
}

// ---------------- fp32 -> fp16 prepass ----------------
__global__ void cvt_f2h(const float* __restrict__ src, int which, int n4) {
    __half* dst = (which == 0) ? g_xh : (which == 1) ? g_wih_h : g_whh_h;
    int i = blockIdx.x * blockDim.x + threadIdx.x;
    if (i < n4) {
        float4 v = ((const float4*)src)[i];
        __half2* dd = (__half2*)dst;
        dd[i * 2]     = __floats2half2_rn(v.x, v.y);
        dd[i * 2 + 1] = __floats2half2_rn(v.z, v.w);
    }
}

// ---------------- HGEMM (NT) + bias: g_gx = A @ W^T + b ----------------
// 128x128 tile, ktile 64, 256 thr (8 warps, 64x32 warp tile), 2-stage cp.async.
#define GA_BYTES (128*72*2)
__global__ __launch_bounds__(GT) void hgemm(int layer, int a_from_seq,
                                            const float* __restrict__ bias_all)
{
    const __half* A = a_from_seq ? g_seqh : g_xh;
    const __half* W = g_wih_h + (size_t)layer * GSZ * HSZ;
    const float* bias = bias_all + (size_t)layer * GSZ;

    extern __shared__ __half smh[];
    uint32_t sb = smem_u32(smh);
    const int tid = threadIdx.x;
    const int mBase = blockIdx.y * 128;
    const int nBase = blockIdx.x * 128;

    auto stage = [&](int kt, int buf) {
        const int kb = kt * 64;
#pragma unroll
        for (int i = 0; i < 4; i++) {
            int u = tid + i * GT; int row = u >> 3, c = u & 7;
            cp16(sb + buf * GA_BYTES + (row * 9 + c) * 16,
                 A + (size_t)(mBase + row) * HSZ + kb + c * 8);
        }
#pragma unroll
        for (int i = 0; i < 4; i++) {
            int u = tid + i * GT; int row = u >> 3, c = u & 7;
            cp16(sb + 2 * GA_BYTES + buf * GA_BYTES + (row * 9 + c) * 16,
                 W + (size_t)(nBase + row) * HSZ + kb + c * 8);
        }
        cp_commit();
    };

    const int w = tid >> 5, lane = tid & 31;
    const int wm = w >> 2, wn = w & 3;
    const int rA = ((lane >> 3) & 1) * 8 + (lane & 7);
    const int kA = lane >> 4;
    const int rB = lane & 7, kB = (lane >> 3) & 1;
    const int grp = lane >> 2, t4 = lane & 3;

    float acc[4][4][4];
#pragma unroll
    for (int a = 0; a < 4; a++)
#pragma unroll
        for (int b2 = 0; b2 < 4; b2++)
#pragma unroll
            for (int c = 0; c < 4; c++) acc[a][b2][c] = 0.f;

    stage(0, 0);
    for (int kt = 0; kt < 16; kt++) {
        if (kt < 15) { stage(kt + 1, (kt + 1) & 1); cp_wait<1>(); }
        else         { cp_wait<0>(); }
        __syncthreads();
        const int buf = kt & 1;
        const uint32_t Ab = sb + buf * GA_BYTES;
        const uint32_t Bb = sb + 2 * GA_BYTES + buf * GA_BYTES;
#pragma unroll
        for (int ks = 0; ks < 4; ks++) {
            uint32_t af[4][4];
#pragma unroll
            for (int mt = 0; mt < 4; mt++)
                ldsm4(af[mt][0], af[mt][1], af[mt][2], af[mt][3],
                      Ab + ((wm * 64 + mt * 16 + rA) * 9 + ks * 2 + kA) * 16);
#pragma unroll
            for (int nt = 0; nt < 4; nt++) {
                uint32_t b0, b1;
                ldsm2(b0, b1, Bb + ((wn * 32 + nt * 8 + rB) * 9 + ks * 2 + kB) * 16);
#pragma unroll
                for (int mt = 0; mt < 4; mt++)
                    mma16816(acc[mt][nt][0], acc[mt][nt][1], acc[mt][nt][2], acc[mt][nt][3],
                             af[mt][0], af[mt][1], af[mt][2], af[mt][3], b0, b1);
            }
        }
        __syncthreads();
    }
#pragma unroll
    for (int mt = 0; mt < 4; mt++) {
        const int m0 = mBase + wm * 64 + mt * 16 + grp;
#pragma unroll
        for (int nt = 0; nt < 4; nt++) {
            const int n0 = nBase + wn * 32 + nt * 8 + t4 * 2;
            const float b0v = bias[n0], b1v = bias[n0 + 1];
            *(float2*)&g_gx[(size_t)m0 * GSZ + n0] =
                make_float2(acc[mt][nt][0] + b0v, acc[mt][nt][1] + b1v);
            *(float2*)&g_gx[(size_t)(m0 + 8) * GSZ + n0] =
                make_float2(acc[mt][nt][2] + b0v, acc[mt][nt][3] + b1v);
        }
    }
}

// ---------------- persistent recurrence (HMMA) ----------------
// Block owns 8 hidden units -> 32 gate cols. G[64,32] = h[64,1024] @ Wslice^T.
#define AS_H (64*1032)
#define BS_H (32*1032)
#define GS_F (64*36)
#define SM_REC_BYTES ((AS_H + BS_H)*2 + (GS_F + 512)*4)
__global__ __launch_bounds__(RT, 1) void lstm_rec(int layer,
    const float* __restrict__ h0, const float* __restrict__ c0,
    float* __restrict__ seq_f32, int write_seq, int write_seqh,
    float* __restrict__ hn, float* __restrict__ cn)
{
    extern __shared__ __half smh[];
    __half* As = smh;
    __half* Bs = smh + AS_H;
    float*  gs = (float*)(smh + AS_H + BS_H);
    float*  cs = gs + GS_F;
    const uint32_t Ab = smem_u32(As);
    const uint32_t Bb = smem_u32(Bs);

    const __half* Wh = g_whh_h + (size_t)layer * GSZ * HSZ;
    const int tid = threadIdx.x;
    const int j0  = blockIdx.x * 8;

    // Whh slice: local col c=q*8+jj  <- row q*H + j0+jj
    for (int idx = tid; idx < 32 * 128; idx += RT) {
        const int rowl = idx >> 7, u = idx & 127;
        const int q = rowl >> 3, jj = rowl & 7;
        *(float4*)(Bs + rowl * 1032 + u * 8) =
            *(const float4*)(Wh + (size_t)(q * HSZ + j0 + jj) * HSZ + u * 8);
    }
    for (int idx = tid; idx < 512; idx += RT) {
        const int r = idx >> 3, jj = idx & 7;
        cs[idx] = c0[(size_t)r * HSZ + j0 + jj];
        g_hbuf[0][r * HSZ + j0 + jj] = __float2half_rn(h0[(size_t)r * HSZ + j0 + jj]);
    }
    grid_barrier();

    const int w = tid >> 5, lane = tid & 31;
    const int mt = w >> 1, nh = w & 1;
    const int rA = ((lane >> 3) & 1) * 8 + (lane & 7);
    const int kA = lane >> 4;
    const int rBa = (lane >> 4) * 8 + (lane & 7);
    const int kBa = (lane >> 3) & 1;
    const int grp = lane >> 2, t4 = lane & 3;

    for (int t = 0; t < T_LEN; t++) {
        const __half* src = g_hbuf[t & 1];
#pragma unroll
        for (int i = 0; i < 16; i++) {
            const int idx = tid + i * RT;
            const int m = idx >> 6, ku = idx & 63;
            cp16(Ab + (m * 129 + ku) * 16, src + (size_t)m * HSZ + ku * 8);
        }
        cp_commit();
#pragma unroll
        for (int i = 0; i < 16; i++) {
            const int idx = tid + i * RT;
            const int m = idx >> 6, ku = 64 + (idx & 63);
            cp16(Ab + (m * 129 + ku) * 16, src + (size_t)m * HSZ + ku * 8);
        }
        cp_commit();

        float acc[2][4] = {{0.f,0.f,0.f,0.f},{0.f,0.f,0.f,0.f}};
        cp_wait<1>();
        __syncthreads();
#pragma unroll 8
        for (int ks = 0; ks < 32; ks++) {
            uint32_t a0, a1, a2, a3, b0, b1, b2, b3;
            ldsm4(a0, a1, a2, a3, Ab + ((mt * 16 + rA) * 129 + ks * 2 + kA) * 16);
            ldsm4(b0, b1, b2, b3, Bb + ((nh * 16 + rBa) * 129 + ks * 2 + kBa) * 16);
            mma16816(acc[0][0], acc[0][1], acc[0][2], acc[0][3], a0, a1, a2, a3, b0, b1);
            mma16816(acc[1][0], acc[1][1], acc[1][2], acc[1][3], a0, a1, a2, a3, b2, b3);
        }
        cp_wait<0>();
        __syncthreads();
#pragma unroll 8
        for (int ks = 32; ks < 64; ks++) {
            uint32_t a0, a1, a2, a3, b0, b1, b2, b3;
            ldsm4(a0, a1, a2, a3, Ab + ((mt * 16 + rA) * 129 + ks * 2 + kA) * 16);
            ldsm4(b0, b1, b2, b3, Bb + ((nh * 16 + rBa) * 129 + ks * 2 + kBa) * 16);
            mma16816(acc[0][0], acc[0][1], acc[0][2], acc[0][3], a0, a1, a2, a3, b0, b1);
            mma16816(acc[1][0], acc[1][1], acc[1][2], acc[1][3], a0, a1, a2, a3, b2, b3);
        }
        __syncthreads();   // gs consumed (step t-1 gating) before overwrite
#pragma unroll
        for (int ntl = 0; ntl < 2; ntl++) {
            const int col = (nh * 2 + ntl) * 8 + t4 * 2;
            gs[(mt * 16 + grp) * 36 + col]     = acc[ntl][0];
            gs[(mt * 16 + grp) * 36 + col + 1] = acc[ntl][1];
            gs[(mt * 16 + grp + 8) * 36 + col]     = acc[ntl][2];
            gs[(mt * 16 + grp + 8) * 36 + col + 1] = acc[ntl][3];
        }
        __syncthreads();

        const float* gxt = g_gx + (size_t)t * BATCH * GSZ;
        const int r = tid >> 2;
        __half* hnext = g_hbuf[(t + 1) & 1];
#pragma unroll
        for (int s = 0; s < 2; s++) {
            const int jj = (tid & 3) * 2 + s;
            const int j = j0 + jj;
            const float* gx = gxt + (size_t)r * GSZ + j;
            float gi = gs[r * 36 + jj]      + gx[0 * HSZ];
            float gf = gs[r * 36 + 8 + jj]  + gx[1 * HSZ];
            float gg = gs[r * 36 + 16 + jj] + gx[2 * HSZ];
            float go = gs[r * 36 + 24 + jj] + gx[3 * HSZ];
            float iv = 1.f / (1.f + __expf(-gi));
            float fv = 1.f / (1.f + __expf(-gf));
            float gv = tanhf(gg);
            float ov = 1.f / (1.f + __expf(-go));
            float cv = fv * cs[r * 8 + jj] + iv * gv;
            float hv = ov * tanhf(cv);
            cs[r * 8 + jj] = cv;
            hnext[r * HSZ + j] = __float2half_rn(hv);
            if (write_seqh) g_seqh[((size_t)t * BATCH + r) * HSZ + j] = __float2half_rn(hv);
            if (write_seq)  seq_f32[((size_t)t * BATCH + r) * HSZ + j] = hv;
            if (t == T_LEN - 1) { hn[r * HSZ + j] = hv; cn[r * HSZ + j] = cv; }
        }
        grid_barrier();
    }
}

// ---------------- launch ----------------
extern "C" void kernel_launch(void* const* d_in, const int* in_sizes, int n_in,
                              void* d_out, int out_size) {
    const float* x   = (const float*)d_in[0];
    const float* Wih = (const float*)d_in[1];
    const float* Whh = (const float*)d_in[2];
    const float* b   = (const float*)d_in[3];
    const float* h0  = (const float*)d_in[4];
    const float* c0  = (const float*)d_in[5];

    float* out     = (float*)d_out;
    float* out_seq = out;
    float* out_hn  = out + (size_t)T_LEN * BATCH * HSZ;
    float* out_cn  = out_hn + (size_t)2 * BATCH * HSZ;

    cudaFuncSetAttribute(hgemm, cudaFuncAttributeMaxDynamicSharedMemorySize, 4 * GA_BYTES);
    cudaFuncSetAttribute(lstm_rec, cudaFuncAttributeMaxDynamicSharedMemorySize, SM_REC_BYTES);

    int n4x = MROWS * HSZ / 4, n4w = 2 * GSZ * HSZ / 4;
    cvt_f2h<<<(n4x + 255) / 256, 256>>>(x, 0, n4x);
    cvt_f2h<<<(n4w + 255) / 256, 256>>>(Wih, 1, n4w);
    cvt_f2h<<<(n4w + 255) / 256, 256>>>(Whh, 2, n4w);

    dim3 ggrid(GSZ / 128, MROWS / 128);
    hgemm<<<ggrid, GT, 4 * GA_BYTES>>>(0, 0, b);
    lstm_rec<<<NBLK, RT, SM_REC_BYTES>>>(0, h0, c0, nullptr, 0, 1, out_hn, out_cn);
    hgemm<<<ggrid, GT, 4 * GA_BYTES>>>(1, 1, b);
    lstm_rec<<<NBLK, RT, SM_REC_BYTES>>>(1, h0 + (size_t)BATCH * HSZ, c0 + (size_t)BATCH * HSZ,
                                         out_seq, 1, 0,
                                         out_hn + (size_t)BATCH * HSZ,
                                         out_cn + (size_t)BATCH * HSZ);
}

// round 7
// speedup vs baseline: 4.3387x; 1.3679x over previous
#include <cuda_runtime.h>
#include <cuda_fp16.h>
#include <cstdint>

#define T_LEN  512
#define BATCH  64
#define HSZ    1024
#define GSZ    4096
#define MROWS  (T_LEN*BATCH)
#define NBLK   128
#define RT     256
#define GT     256

// lstm_rec smem layout (bytes): A[64][1032]h, B[32][1032]h, gs[4][64][33]f
#define A_OFF   0
#define B_OFF   132096
#define GS_OFF  198144
#define GS_ROW  33
#define GS_BUF  (64*GS_ROW)          // floats per ki buffer
#define SM_REC_BYTES (GS_OFF + 4*GS_BUF*4)   // 231936 <= 232448

// ---------------- scratch ----------------
__device__ __half g_xh  [(size_t)MROWS*HSZ];
__device__ __half g_seqh[(size_t)MROWS*HSZ];
__device__ __half g_wih_h[(size_t)2*GSZ*HSZ];
__device__ __half g_whh_h[(size_t)2*GSZ*HSZ];
__device__ float  g_gx  [(size_t)MROWS*GSZ];
__device__ __half g_hbuf[2][BATCH*HSZ];
__device__ unsigned g_cnt;
__device__ volatile unsigned g_gen;

// ---------------- ptx helpers ----------------
__device__ __forceinline__ uint32_t smem_u32(const void* p) {
    uint32_t a;
    asm("{ .reg .u64 t; cvta.to.shared.u64 t, %1; cvt.u32.u64 %0, t; }" : "=r"(a) : "l"(p));
    return a;
}
__device__ __forceinline__ void cp16(uint32_t d, const void* s) {
    asm volatile("cp.async.cg.shared.global [%0], [%1], 16;" :: "r"(d), "l"(s));
}
__device__ __forceinline__ void cp_commit() { asm volatile("cp.async.commit_group;"); }
template<int N> __device__ __forceinline__ void cp_wait() {
    asm volatile("cp.async.wait_group %0;" :: "n"(N));
}
__device__ __forceinline__ void ldsm4(uint32_t& r0, uint32_t& r1, uint32_t& r2, uint32_t& r3, uint32_t a) {
    asm volatile("ldmatrix.sync.aligned.m8n8.x4.shared.b16 {%0,%1,%2,%3}, [%4];"
        : "=r"(r0), "=r"(r1), "=r"(r2), "=r"(r3) : "r"(a));
}
__device__ __forceinline__ void ldsm2(uint32_t& r0, uint32_t& r1, uint32_t a) {
    asm volatile("ldmatrix.sync.aligned.m8n8.x2.shared.b16 {%0,%1}, [%2];"
        : "=r"(r0), "=r"(r1) : "r"(a));
}
__device__ __forceinline__ void mma16816(float& c0, float& c1, float& c2, float& c3,
    uint32_t a0, uint32_t a1, uint32_t a2, uint32_t a3, uint32_t b0, uint32_t b1) {
    asm volatile("mma.sync.aligned.m16n8k16.row.col.f32.f16.f16.f32 "
        "{%0,%1,%2,%3}, {%4,%5,%6,%7}, {%8,%9}, {%0,%1,%2,%3};"
        : "+f"(c0), "+f"(c1), "+f"(c2), "+f"(c3)
        : "r"(a0), "r"(a1), "r"(a2), "r"(a3), "r"(b0), "r"(b1));
}
__device__ __forceinline__ void grid_barrier() {
    __threadfence();
    __syncthreads();
    if (threadIdx.x == 0) {
        unsigned mygen = g_gen;
        unsigned prev = atomicAdd(&g_cnt, 1u);
        if (prev == (unsigned)(NBLK - 1)) {
            g_cnt = 0; __threadfence(); g_gen = mygen + 1u;
        } else {
            while (g_gen == mygen) {}
        }
        __threadfence();
    }
    __syncthreads();
}

// ---------------- fp32 -> fp16 prepass ----------------
__global__ void cvt_f2h(const float* __restrict__ src, int which, int n4) {
    __half* dst = (which == 0) ? g_xh : (which == 1) ? g_wih_h : g_whh_h;
    int i = blockIdx.x * blockDim.x + threadIdx.x;
    if (i < n4) {
        float4 v = ((const float4*)src)[i];
        __half2* dd = (__half2*)dst;
        dd[i * 2]     = __floats2half2_rn(v.x, v.y);
        dd[i * 2 + 1] = __floats2half2_rn(v.z, v.w);
    }
}

// ---------------- HGEMM (NT) + bias (validated in R3/R4) ----------------
#define GA_BYTES (128*72*2)
__global__ __launch_bounds__(GT) void hgemm(int layer, int a_from_seq,
                                            const float* __restrict__ bias_all)
{
    const __half* A = a_from_seq ? g_seqh : g_xh;
    const __half* W = g_wih_h + (size_t)layer * GSZ * HSZ;
    const float* bias = bias_all + (size_t)layer * GSZ;

    extern __shared__ __half smh[];
    uint32_t sb = smem_u32(smh);
    const int tid = threadIdx.x;
    const int mBase = blockIdx.y * 128;
    const int nBase = blockIdx.x * 128;

    auto stage = [&](int kt, int buf) {
        const int kb = kt * 64;
#pragma unroll
        for (int i = 0; i < 4; i++) {
            int u = tid + i * GT; int row = u >> 3, c = u & 7;
            cp16(sb + buf * GA_BYTES + (row * 9 + c) * 16,
                 A + (size_t)(mBase + row) * HSZ + kb + c * 8);
        }
#pragma unroll
        for (int i = 0; i < 4; i++) {
            int u = tid + i * GT; int row = u >> 3, c = u & 7;
            cp16(sb + 2 * GA_BYTES + buf * GA_BYTES + (row * 9 + c) * 16,
                 W + (size_t)(nBase + row) * HSZ + kb + c * 8);
        }
        cp_commit();
    };

    const int w = tid >> 5, lane = tid & 31;
    const int wm = w >> 2, wn = w & 3;
    const int rA = ((lane >> 3) & 1) * 8 + (lane & 7);
    const int kA = lane >> 4;
    const int rB = lane & 7, kB = (lane >> 3) & 1;
    const int grp = lane >> 2, t4 = lane & 3;

    float acc[4][4][4];
#pragma unroll
    for (int a = 0; a < 4; a++)
#pragma unroll
        for (int b2 = 0; b2 < 4; b2++)
#pragma unroll
            for (int c = 0; c < 4; c++) acc[a][b2][c] = 0.f;

    stage(0, 0);
    for (int kt = 0; kt < 16; kt++) {
        if (kt < 15) { stage(kt + 1, (kt + 1) & 1); cp_wait<1>(); }
        else         { cp_wait<0>(); }
        __syncthreads();
        const int buf = kt & 1;
        const uint32_t Ab = sb + buf * GA_BYTES;
        const uint32_t Bb = sb + 2 * GA_BYTES + buf * GA_BYTES;
#pragma unroll
        for (int ks = 0; ks < 4; ks++) {
            uint32_t af[4][4];
#pragma unroll
            for (int mt = 0; mt < 4; mt++)
                ldsm4(af[mt][0], af[mt][1], af[mt][2], af[mt][3],
                      Ab + ((wm * 64 + mt * 16 + rA) * 9 + ks * 2 + kA) * 16);
#pragma unroll
            for (int nt = 0; nt < 4; nt++) {
                uint32_t b0, b1;
                ldsm2(b0, b1, Bb + ((wn * 32 + nt * 8 + rB) * 9 + ks * 2 + kB) * 16);
#pragma unroll
                for (int mt = 0; mt < 4; mt++)
                    mma16816(acc[mt][nt][0], acc[mt][nt][1], acc[mt][nt][2], acc[mt][nt][3],
                             af[mt][0], af[mt][1], af[mt][2], af[mt][3], b0, b1);
            }
        }
        __syncthreads();
    }
#pragma unroll
    for (int mt = 0; mt < 4; mt++) {
        const int m0 = mBase + wm * 64 + mt * 16 + grp;
#pragma unroll
        for (int nt = 0; nt < 4; nt++) {
            const int n0 = nBase + wn * 32 + nt * 8 + t4 * 2;
            const float b0v = bias[n0], b1v = bias[n0 + 1];
            *(float2*)&g_gx[(size_t)m0 * GSZ + n0] =
                make_float2(acc[mt][nt][0] + b0v, acc[mt][nt][1] + b1v);
            *(float2*)&g_gx[(size_t)(m0 + 8) * GSZ + n0] =
                make_float2(acc[mt][nt][2] + b0v, acc[mt][nt][3] + b1v);
        }
    }
}

// ---------------- persistent recurrence (mma.sync, crossbar-minimal) ----------------
// Block owns 8 units -> 32 gate cols. G[64,32] = h[64,1024] @ Wslice^T.
// 8 warps = (mi 0..1) x (ki 0..3): warp tile 32 rows x 32 cols, K-chunk 256.
// A read 1x, B read 2x. K-partials reduced via 4 smem buffers.
__global__ __launch_bounds__(RT, 1) void lstm_rec(int layer,
    const float* __restrict__ h0, const float* __restrict__ c0,
    float* __restrict__ seq_f32, int write_seq, int write_seqh,
    float* __restrict__ hn, float* __restrict__ cn)
{
    extern __shared__ char sm[];
    __half* As = (__half*)(sm + A_OFF);     // [64][1032]
    __half* Bs = (__half*)(sm + B_OFF);     // [32][1032]
    float*  gs = (float*)(sm + GS_OFF);     // [4][64][33]
    const uint32_t Ab = smem_u32(As);
    const uint32_t Bb = smem_u32(Bs);

    const __half* Wh = g_whh_h + (size_t)layer * GSZ * HSZ;
    const int tid = threadIdx.x, wid = tid >> 5, lane = tid & 31;
    const int j0 = blockIdx.x * 8;

    // ---- B: Whh slice [32 x 1024] -> smem rows (col n = q*8+jj <- Whh row q*H+j0+jj)
    for (int idx = tid; idx < 32 * 128; idx += RT) {
        const int n = idx >> 7, u = idx & 127;
        const int q = n >> 3, jj = n & 7;
        *(uint4*)(Bs + n * 1032 + u * 8) =
            *(const uint4*)(Wh + (size_t)(q * HSZ + j0 + jj) * HSZ + u * 8);
    }
    // ---- init h(0) fp16 and c-state (registers of gating threads) ----
    for (int idx = tid; idx < 512; idx += RT) {
        const int r = idx >> 3, jj = idx & 7;
        g_hbuf[0][r * HSZ + j0 + jj] = __float2half_rn(h0[(size_t)r * HSZ + j0 + jj]);
    }
    float cr[8];
    if (tid < 64) {
#pragma unroll
        for (int jj = 0; jj < 8; jj++) cr[jj] = c0[(size_t)tid * HSZ + j0 + jj];
    }
    grid_barrier();

    const int mi = wid >> 2;            // 0..1 : rows mi*32..+32
    const int ki = wid & 3;             // 0..3 : k-units ki*16..+16
    const int rA = ((lane >> 3) & 1) * 8 + (lane & 7);
    const int kA = lane >> 4;
    const int rB = (lane >> 4) * 8 + (lane & 7);
    const int kB = (lane >> 3) & 1;
    const int grp = lane >> 2, t4 = lane & 3;
    float* gsk = gs + ki * GS_BUF;

    for (int t = 0; t < T_LEN; t++) {
        const __half* src = g_hbuf[t & 1];

        // gx prefetch into registers (gating threads) - latency hidden by MMA
        float gxv[4][8];
        if (tid < 64) {
            const float* gp = g_gx + (size_t)t * BATCH * GSZ + (size_t)tid * GSZ + j0;
#pragma unroll
            for (int q = 0; q < 4; q++) {
                *(float4*)&gxv[q][0] = __ldg((const float4*)(gp + q * HSZ));
                *(float4*)&gxv[q][4] = __ldg((const float4*)(gp + q * HSZ + 4));
            }
        }

        // load full A tile (h, 64x1024 fp16): 8192 cp16 / 256 thr
#pragma unroll
        for (int i = 0; i < 32; i++) {
            const int idx = tid + i * RT;
            const int r = idx >> 7, u = idx & 127;
            cp16(Ab + (r * 129 + u) * 16, src + (size_t)r * HSZ + u * 8);
        }
        cp_commit();
        cp_wait<0>();
        __syncthreads();

        // MMA: warp (mi,ki): C_part[32x32] over k = ki*256..+256
        float acc[2][4][4];
#pragma unroll
        for (int a = 0; a < 2; a++)
#pragma unroll
            for (int b2 = 0; b2 < 4; b2++)
#pragma unroll
                for (int c = 0; c < 4; c++) acc[a][b2][c] = 0.f;

#pragma unroll 4
        for (int s = 0; s < 16; s++) {
            const int ks = ki * 16 + s;
            uint32_t a0[2][4], bf[2][4];
#pragma unroll
            for (int ma = 0; ma < 2; ma++)
                ldsm4(a0[ma][0], a0[ma][1], a0[ma][2], a0[ma][3],
                      Ab + ((mi * 32 + ma * 16 + rA) * 129 + ks * 2 + kA) * 16);
#pragma unroll
            for (int nt = 0; nt < 2; nt++)
                ldsm4(bf[nt][0], bf[nt][1], bf[nt][2], bf[nt][3],
                      Bb + ((nt * 16 + rB) * 129 + ks * 2 + kB) * 16);
#pragma unroll
            for (int ma = 0; ma < 2; ma++)
#pragma unroll
                for (int nt = 0; nt < 2; nt++) {
                    mma16816(acc[ma][nt*2][0], acc[ma][nt*2][1], acc[ma][nt*2][2], acc[ma][nt*2][3],
                             a0[ma][0], a0[ma][1], a0[ma][2], a0[ma][3], bf[nt][0], bf[nt][1]);
                    mma16816(acc[ma][nt*2+1][0], acc[ma][nt*2+1][1], acc[ma][nt*2+1][2], acc[ma][nt*2+1][3],
                             a0[ma][0], a0[ma][1], a0[ma][2], a0[ma][3], bf[nt][2], bf[nt][3]);
                }
        }

        // store K-partials (gs was fully consumed before the barrier of step t-1)
#pragma unroll
        for (int ma = 0; ma < 2; ma++) {
            const int row = mi * 32 + ma * 16 + grp;
#pragma unroll
            for (int nb = 0; nb < 4; nb++) {
                const int col = nb * 8 + t4 * 2;
                gsk[row * GS_ROW + col]     = acc[ma][nb][0];
                gsk[row * GS_ROW + col + 1] = acc[ma][nb][1];
                gsk[(row + 8) * GS_ROW + col]     = acc[ma][nb][2];
                gsk[(row + 8) * GS_ROW + col + 1] = acc[ma][nb][3];
            }
        }
        __syncthreads();

        // gating: thread r < 64 handles its batch row (8 units)
        if (tid < 64) {
            const int r = tid;
            __half hh[8];
            float hvf[8];
#pragma unroll
            for (int jj = 0; jj < 8; jj++) {
#pragma unroll
                for (int q_unused = 0; q_unused < 1; q_unused++) {} // keep unroll shape simple
                float pre[4];
#pragma unroll
                for (int q = 0; q < 4; q++) {
                    const int c = q * 8 + jj;
                    pre[q] = gs[0 * GS_BUF + r * GS_ROW + c]
                           + gs[1 * GS_BUF + r * GS_ROW + c]
                           + gs[2 * GS_BUF + r * GS_ROW + c]
                           + gs[3 * GS_BUF + r * GS_ROW + c]
                           + gxv[q][jj];
                }
                const float iv = 1.f / (1.f + __expf(-pre[0]));
                const float fv = 1.f / (1.f + __expf(-pre[1]));
                const float gv = tanhf(pre[2]);
                const float ov = 1.f / (1.f + __expf(-pre[3]));
                const float cv = fv * cr[jj] + iv * gv;
                const float hv = ov * tanhf(cv);
                cr[jj] = cv;
                hh[jj] = __float2half_rn(hv);
                hvf[jj] = hv;
            }
            __half* hnext = g_hbuf[(t + 1) & 1];
            *(uint4*)(hnext + (size_t)r * HSZ + j0) = *(uint4*)hh;
            if (write_seqh)
                *(uint4*)(g_seqh + ((size_t)t * BATCH + r) * HSZ + j0) = *(uint4*)hh;
            if (write_seq) {
                *(float4*)(seq_f32 + ((size_t)t * BATCH + r) * HSZ + j0) = *(float4*)&hvf[0];
                *(float4*)(seq_f32 + ((size_t)t * BATCH + r) * HSZ + j0 + 4) = *(float4*)&hvf[4];
            }
            if (t == T_LEN - 1) {
#pragma unroll
                for (int jj = 0; jj < 8; jj++) {
                    hn[(size_t)r * HSZ + j0 + jj] = hvf[jj];
                    cn[(size_t)r * HSZ + j0 + jj] = cr[jj];
                }
            }
        }
        grid_barrier();
    }
}

// ---------------- launch ----------------
extern "C" void kernel_launch(void* const* d_in, const int* in_sizes, int n_in,
                              void* d_out, int out_size) {
    const float* x   = (const float*)d_in[0];
    const float* Wih = (const float*)d_in[1];
    const float* Whh = (const float*)d_in[2];
    const float* b   = (const float*)d_in[3];
    const float* h0  = (const float*)d_in[4];
    const float* c0  = (const float*)d_in[5];

    float* out     = (float*)d_out;
    float* out_seq = out;
    float* out_hn  = out + (size_t)T_LEN * BATCH * HSZ;
    float* out_cn  = out_hn + (size_t)2 * BATCH * HSZ;

    cudaFuncSetAttribute(hgemm, cudaFuncAttributeMaxDynamicSharedMemorySize, 4 * GA_BYTES);
    cudaFuncSetAttribute(lstm_rec, cudaFuncAttributeMaxDynamicSharedMemorySize, SM_REC_BYTES);

    int n4x = MROWS * HSZ / 4, n4w = 2 * GSZ * HSZ / 4;
    cvt_f2h<<<(n4x + 255) / 256, 256>>>(x, 0, n4x);
    cvt_f2h<<<(n4w + 255) / 256, 256>>>(Wih, 1, n4w);
    cvt_f2h<<<(n4w + 255) / 256, 256>>>(Whh, 2, n4w);

    dim3 ggrid(GSZ / 128, MROWS / 128);
    hgemm<<<ggrid, GT, 4 * GA_BYTES>>>(0, 0, b);
    lstm_rec<<<NBLK, RT, SM_REC_BYTES>>>(0, h0, c0, nullptr, 0, 1, out_hn, out_cn);
    hgemm<<<ggrid, GT, 4 * GA_BYTES>>>(1, 1, b);
    lstm_rec<<<NBLK, RT, SM_REC_BYTES>>>(1, h0 + (size_t)BATCH * HSZ, c0 + (size_t)BATCH * HSZ,
                                         out_seq, 1, 0,
                                         out_hn + (size_t)BATCH * HSZ,
                                         out_cn + (size_t)BATCH * HSZ);
}